// round 1
// baseline (speedup 1.0000x reference)
#include <cuda_runtime.h>
#include <math.h>

#define B       32
#define NP      22536
#define NC      81
#define NOBJ    16
#define PRIORS_PER_BLOCK 72     // 22536 = 313 * 72
#define ITERS            9      // 72 / 8 warps
#define NCHUNK           313

__device__ unsigned long long g_obj_key[B * NOBJ];
__device__ double g_sum_loc;
__device__ double g_sum_focal;
__device__ unsigned int g_n_pos;
__device__ unsigned int g_n_inc;

// ---------------------------------------------------------------------------
// Kernel 0: zero the scratch accumulators (deterministic per launch)
// ---------------------------------------------------------------------------
__global__ void k_init() {
    int t = threadIdx.x;
    if (t < B * NOBJ) g_obj_key[t] = 0ULL;
    if (t == 0) {
        g_sum_loc = 0.0;
        g_sum_focal = 0.0;
        g_n_pos = 0u;
        g_n_inc = 0u;
    }
}

// ---------------------------------------------------------------------------
// Kernel 1: per-object best prior  (prior_obj[i] = argmax_p IoU(box_i, prior_p))
// Key packs (iou_bits << 32) | (0xFFFFFFFF - p): max key == max iou, and among
// equal ious the SMALLEST prior index wins (matches jnp.argmax first-occurrence).
// ---------------------------------------------------------------------------
__global__ void __launch_bounds__(256) k_match(const float4* __restrict__ boxes,
                                               const float4* __restrict__ priors) {
    const int b = blockIdx.x;
    __shared__ float4 bx[NOBJ];
    __shared__ float  ba[NOBJ];
    __shared__ unsigned long long sbest[NOBJ];
    if (threadIdx.x < NOBJ) {
        float4 v = boxes[b * NOBJ + threadIdx.x];
        bx[threadIdx.x] = v;
        ba[threadIdx.x] = (v.z - v.x) * (v.w - v.y);
        sbest[threadIdx.x] = 0ULL;
    }
    __syncthreads();

    unsigned long long best[NOBJ];
#pragma unroll
    for (int i = 0; i < NOBJ; i++) best[i] = 0ULL;

    const int stride = blockDim.x * gridDim.y;
    for (int p = blockIdx.y * blockDim.x + threadIdx.x; p < NP; p += stride) {
        float4 pc = priors[p];
        float p1x = pc.x - pc.z * 0.5f, p1y = pc.y - pc.w * 0.5f;
        float p2x = pc.x + pc.z * 0.5f, p2y = pc.y + pc.w * 0.5f;
        float parea = (p2x - p1x) * (p2y - p1y);
        unsigned long long plow =
            (unsigned long long)(0xFFFFFFFFu - (unsigned)p);
#pragma unroll
        for (int i = 0; i < NOBJ; i++) {
            float lx = fmaxf(bx[i].x, p1x), ly = fmaxf(bx[i].y, p1y);
            float hx = fminf(bx[i].z, p2x), hy = fminf(bx[i].w, p2y);
            float inter = fmaxf(hx - lx, 0.0f) * fmaxf(hy - ly, 0.0f);
            float iou = inter / (ba[i] + parea - inter);
            unsigned long long key =
                ((unsigned long long)__float_as_uint(iou) << 32) | plow;
            if (key > best[i]) best[i] = key;
        }
    }
#pragma unroll
    for (int i = 0; i < NOBJ; i++) atomicMax(&sbest[i], best[i]);
    __syncthreads();
    if (threadIdx.x < NOBJ)
        atomicMax(&g_obj_key[b * NOBJ + threadIdx.x], sbest[threadIdx.x]);
}

// ---------------------------------------------------------------------------
// Kernel 2: per-prior label/match, focal loss and DIoU loc loss.
// One warp per prior, 8 priors per block-iteration, 72 priors per block.
// ---------------------------------------------------------------------------
__global__ void __launch_bounds__(256) k_main(const float4* __restrict__ locs,
                                              const float*  __restrict__ scores,
                                              const float4* __restrict__ boxes,
                                              const int*    __restrict__ labels,
                                              const float4* __restrict__ priors) {
    const int b = blockIdx.y;
    const int chunk = blockIdx.x;      // 0..312
    __shared__ float  ssc[8 * NC];     // staged score rows for 8 priors
    __shared__ float4 sbx[NOBJ];
    __shared__ float  sba[NOBJ];
    __shared__ int    slab[NOBJ];
    __shared__ int    sop[NOBJ];       // per-object best prior
    __shared__ float  red_loc[8], red_foc[8];
    __shared__ int    red_pos[8], red_inc[8];

    const int t = threadIdx.x;
    const int w = t >> 5;
    const int lane = t & 31;

    if (t < NOBJ) {
        float4 v = boxes[b * NOBJ + t];
        sbx[t] = v;
        sba[t] = (v.z - v.x) * (v.w - v.y);
        slab[t] = labels[b * NOBJ + t];
        unsigned long long k = g_obj_key[b * NOBJ + t];
        sop[t] = (int)(0xFFFFFFFFu - (unsigned)(k & 0xFFFFFFFFULL));
    }

    float acc_loc = 0.0f, acc_foc = 0.0f;
    int cnt_pos = 0, cnt_inc = 0;

    for (int it = 0; it < ITERS; it++) {
        const int p0 = chunk * PRIORS_PER_BLOCK + it * 8;
        __syncthreads();   // covers sbx on it==0, protects ssc rewrite after
        const float* src = scores + ((long long)b * NP + p0) * NC;
        for (int i = t; i < 8 * NC; i += 256) ssc[i] = src[i];
        __syncthreads();

        const int p = p0 + w;
        const float4 pc = priors[p];
        const float p1x = pc.x - pc.z * 0.5f, p1y = pc.y - pc.w * 0.5f;
        const float p2x = pc.x + pc.z * 0.5f, p2y = pc.y + pc.w * 0.5f;
        const float parea = (p2x - p1x) * (p2y - p1y);

        // lane i (<16) computes IoU with object i
        float iou = -1.0f;
        int obj = NOBJ;
        if (lane < NOBJ) {
            float4 bxv = sbx[lane];
            float lx = fmaxf(bxv.x, p1x), ly = fmaxf(bxv.y, p1y);
            float hx = fminf(bxv.z, p2x), hy = fminf(bxv.w, p2y);
            float inter = fmaxf(hx - lx, 0.0f) * fmaxf(hy - ly, 0.0f);
            iou = inter / (sba[lane] + parea - inter);
            obj = lane;
        }
        // warp reduce: max iou, smallest object index on ties
#pragma unroll
        for (int off = 16; off; off >>= 1) {
            float oi = __shfl_xor_sync(0xFFFFFFFFu, iou, off);
            int   oo = __shfl_xor_sync(0xFFFFFFFFu, obj, off);
            if (oi > iou || (oi == iou && oo < obj)) { iou = oi; obj = oo; }
        }
        // forced-match override: largest object index whose best prior == p
        int mi = (lane < NOBJ && sop[lane] == p) ? lane : -1;
#pragma unroll
        for (int off = 16; off; off >>= 1)
            mi = max(mi, __shfl_xor_sync(0xFFFFFFFFu, mi, off));
        if (mi >= 0) { obj = mi; iou = 1.0f; }

        int lab = slab[obj];
        if (iou < 0.5f)         lab = -1;
        if (iou < 0.5f - 0.1f)  lab = 0;
        const bool inc = (lab >= 0);
        const int tcls = (lab < 0) ? 0 : lab;

        // warp log-sum-exp over the 81 staged scores
        const float* row = ssc + w * NC;
        float v0 = row[lane];
        float v1 = row[lane + 32];
        float v2 = (lane < NC - 64) ? row[lane + 64] : -INFINITY;
        float m = fmaxf(fmaxf(v0, v1), v2);
#pragma unroll
        for (int off = 16; off; off >>= 1)
            m = fmaxf(m, __shfl_xor_sync(0xFFFFFFFFu, m, off));
        float s = expf(v0 - m) + expf(v1 - m) +
                  ((lane < NC - 64) ? expf(v2 - m) : 0.0f);
#pragma unroll
        for (int off = 16; off; off >>= 1)
            s += __shfl_xor_sync(0xFFFFFFFFu, s, off);

        if (lane == 0) {
            if (inc) {
                float logpt = row[tcls] - m - logf(s);
                float pt = expf(logpt);
                float om = 1.0f - pt;
                acc_foc += -om * om * logpt;
                cnt_inc++;
            }
            if (lab > 0) {
                // decode prediction to corner box
                float4 g = locs[(long long)b * NP + p];
                float cx = g.x * pc.z * 0.1f + pc.x;
                float cy = g.y * pc.w * 0.1f + pc.y;
                float wd = expf(g.z * 0.2f) * pc.z;
                float ht = expf(g.w * 0.2f) * pc.w;
                float dx1 = cx - wd * 0.5f, dy1 = cy - ht * 0.5f;
                float dx2 = cx + wd * 0.5f, dy2 = cy + ht * 0.5f;
                float4 tb = sbx[obj];
                // DIoU
                float lx = fmaxf(dx1, tb.x), ly = fmaxf(dy1, tb.y);
                float hx = fminf(dx2, tb.z), hy = fminf(dy2, tb.w);
                float inter = fmaxf(hx - lx, 0.0f) * fmaxf(hy - ly, 0.0f);
                float ap = (dx2 - dx1) * (dy2 - dy1);
                float at = (tb.z - tb.x) * (tb.w - tb.y);
                float iou2 = inter / (ap + at - inter);
                float pcx = (dx1 + dx2) * 0.5f, pcy = (dy1 + dy2) * 0.5f;
                float tcx = (tb.x + tb.z) * 0.5f, tcy = (tb.y + tb.w) * 0.5f;
                float ddx = pcx - tcx, ddy = pcy - tcy;
                float idiag = ddx * ddx + ddy * ddy;
                float ox = fmaxf(fmaxf(dx2, tb.z) - fminf(dx1, tb.x), 0.0f);
                float oy = fmaxf(fmaxf(dy2, tb.w) - fminf(dy1, tb.y), 0.0f);
                float odiag = ox * ox + oy * oy;
                float d = iou2 - idiag / odiag;
                d = fminf(fmaxf(d, -1.0f), 1.0f);
                acc_loc += 1.0f - d;
                cnt_pos++;
            }
        }
    }

    if (lane == 0) {
        red_loc[w] = acc_loc;
        red_foc[w] = acc_foc;
        red_pos[w] = cnt_pos;
        red_inc[w] = cnt_inc;
    }
    __syncthreads();
    if (t == 0) {
        float sl = 0.0f, sf = 0.0f;
        int sp = 0, si = 0;
#pragma unroll
        for (int i = 0; i < 8; i++) {
            sl += red_loc[i]; sf += red_foc[i];
            sp += red_pos[i]; si += red_inc[i];
        }
        atomicAdd(&g_sum_loc, (double)sl);
        atomicAdd(&g_sum_focal, (double)sf);
        atomicAdd(&g_n_pos, (unsigned)sp);
        atomicAdd(&g_n_inc, (unsigned)si);
    }
}

// ---------------------------------------------------------------------------
// Kernel 3: finalize scalar loss
// ---------------------------------------------------------------------------
__global__ void k_final(float* out) {
    double np = (double)g_n_pos;
    double conf = (g_sum_focal / (double)g_n_inc) / np;
    double loc = g_sum_loc / np;
    out[0] = (float)(conf + 25.0 * loc);
}

// ---------------------------------------------------------------------------
extern "C" void kernel_launch(void* const* d_in, const int* in_sizes, int n_in,
                              void* d_out, int out_size) {
    const float4* locs   = (const float4*)d_in[0];
    const float*  scores = (const float*)d_in[1];
    const float4* boxes  = (const float4*)d_in[2];
    const int*    labels = (const int*)d_in[3];
    const float4* priors = (const float4*)d_in[4];

    k_init<<<1, 512>>>();
    k_match<<<dim3(B, 8), 256>>>(boxes, priors);
    k_main<<<dim3(NCHUNK, B), 256>>>(locs, scores, boxes, labels, priors);
    k_final<<<1, 1>>>((float*)d_out);
}

// round 3
// speedup vs baseline: 1.1322x; 1.1322x over previous
#include <cuda_runtime.h>
#include <math.h>

#define B       32
#define NP      22536
#define NC      81
#define NOBJ    16
#define NBLKX   352     // blocks per batch image; 8 warps each -> 2816 warps/image

__device__ unsigned long long g_obj_key[B * NOBJ];
__device__ double g_sum_loc;
__device__ double g_sum_focal;
__device__ unsigned int g_n_pos;
__device__ unsigned int g_n_inc;

// ---------------------------------------------------------------------------
// Kernel 0: zero the scratch accumulators
// ---------------------------------------------------------------------------
__global__ void k_init() {
    int t = threadIdx.x;
    if (t < B * NOBJ) g_obj_key[t] = 0ULL;
    if (t == 0) {
        g_sum_loc = 0.0;
        g_sum_focal = 0.0;
        g_n_pos = 0u;
        g_n_inc = 0u;
    }
}

// ---------------------------------------------------------------------------
// Kernel 1: per-object best prior (argmax over priors, first-occurrence ties)
// ---------------------------------------------------------------------------
__global__ void __launch_bounds__(256) k_match(const float4* __restrict__ boxes,
                                               const float4* __restrict__ priors) {
    const int b = blockIdx.x;
    __shared__ float4 bx[NOBJ];
    __shared__ float  ba[NOBJ];
    __shared__ unsigned long long sbest[NOBJ];
    if (threadIdx.x < NOBJ) {
        float4 v = boxes[b * NOBJ + threadIdx.x];
        bx[threadIdx.x] = v;
        ba[threadIdx.x] = (v.z - v.x) * (v.w - v.y);
        sbest[threadIdx.x] = 0ULL;
    }
    __syncthreads();

    unsigned long long best[NOBJ];
#pragma unroll
    for (int i = 0; i < NOBJ; i++) best[i] = 0ULL;

    const int stride = blockDim.x * gridDim.y;
    for (int p = blockIdx.y * blockDim.x + threadIdx.x; p < NP; p += stride) {
        float4 pc = priors[p];
        float p1x = pc.x - pc.z * 0.5f, p1y = pc.y - pc.w * 0.5f;
        float p2x = pc.x + pc.z * 0.5f, p2y = pc.y + pc.w * 0.5f;
        float parea = (p2x - p1x) * (p2y - p1y);
        unsigned long long plow =
            (unsigned long long)(0xFFFFFFFFu - (unsigned)p);
#pragma unroll
        for (int i = 0; i < NOBJ; i++) {
            float lx = fmaxf(bx[i].x, p1x), ly = fmaxf(bx[i].y, p1y);
            float hx = fminf(bx[i].z, p2x), hy = fminf(bx[i].w, p2y);
            float inter = fmaxf(hx - lx, 0.0f) * fmaxf(hy - ly, 0.0f);
            float iou = inter / (ba[i] + parea - inter);
            unsigned long long key =
                ((unsigned long long)__float_as_uint(iou) << 32) | plow;
            if (key > best[i]) best[i] = key;
        }
    }
#pragma unroll
    for (int i = 0; i < NOBJ; i++) atomicMax(&sbest[i], best[i]);
    __syncthreads();
    if (threadIdx.x < NOBJ)
        atomicMax(&g_obj_key[b * NOBJ + threadIdx.x], sbest[threadIdx.x]);
}

// ---------------------------------------------------------------------------
// Kernel 2: per-prior label/match, focal loss and DIoU loc loss.
// One warp per prior; warps loop independently (no barriers, no SMEM staging):
// the 81-class score row is read directly with 3 coalesced loads per lane.
// ---------------------------------------------------------------------------
__global__ void __launch_bounds__(256, 6) k_main(const float4* __restrict__ locs,
                                                 const float*  __restrict__ scores,
                                                 const float4* __restrict__ boxes,
                                                 const int*    __restrict__ labels,
                                                 const float4* __restrict__ priors) {
    const int b = blockIdx.y;
    __shared__ float4 sbx[NOBJ];
    __shared__ float  sba[NOBJ];
    __shared__ int    slab[NOBJ];
    __shared__ int    sop[NOBJ];
    __shared__ float  red_loc[8], red_foc[8];
    __shared__ int    red_pos[8], red_inc[8];

    const int t = threadIdx.x;
    const int w = t >> 5;
    const int lane = t & 31;

    if (t < NOBJ) {
        float4 v = boxes[b * NOBJ + t];
        sbx[t] = v;
        sba[t] = (v.z - v.x) * (v.w - v.y);
        slab[t] = labels[b * NOBJ + t];
        unsigned long long k = g_obj_key[b * NOBJ + t];
        sop[t] = (int)(0xFFFFFFFFu - (unsigned)(k & 0xFFFFFFFFULL));
    }
    __syncthreads();

    float acc_loc = 0.0f, acc_foc = 0.0f;
    int cnt_pos = 0, cnt_inc = 0;

    const int wstride = 8 * gridDim.x;
    const float* sbase = scores + (long long)b * NP * NC;
    const float4* lbase = locs + (long long)b * NP;

    for (int p = blockIdx.x * 8 + w; p < NP; p += wstride) {
        const float* row = sbase + (long long)p * NC;
        // issue score loads first: 3 coalesced 128B transactions per warp
        float v0 = __ldg(row + lane);
        float v1 = __ldg(row + lane + 32);
        float v2 = (lane < NC - 64) ? __ldg(row + lane + 64) : -INFINITY;

        const float4 pc = __ldg(priors + p);
        const float p1x = pc.x - pc.z * 0.5f, p1y = pc.y - pc.w * 0.5f;
        const float p2x = pc.x + pc.z * 0.5f, p2y = pc.y + pc.w * 0.5f;
        const float parea = (p2x - p1x) * (p2y - p1y);

        // lane i (<16) computes IoU with object i
        float iou = -1.0f;
        int obj = NOBJ;
        if (lane < NOBJ) {
            float4 bxv = sbx[lane];
            float lx = fmaxf(bxv.x, p1x), ly = fmaxf(bxv.y, p1y);
            float hx = fminf(bxv.z, p2x), hy = fminf(bxv.w, p2y);
            float inter = fmaxf(hx - lx, 0.0f) * fmaxf(hy - ly, 0.0f);
            iou = inter / (sba[lane] + parea - inter);
            obj = lane;
        }
        // warp reduce: max iou, smallest object index on ties
#pragma unroll
        for (int off = 16; off; off >>= 1) {
            float oi = __shfl_xor_sync(0xFFFFFFFFu, iou, off);
            int   oo = __shfl_xor_sync(0xFFFFFFFFu, obj, off);
            if (oi > iou || (oi == iou && oo < obj)) { iou = oi; obj = oo; }
        }
        // forced-match override: largest object index whose best prior == p
        int mi = (lane < NOBJ && sop[lane] == p) ? lane : -1;
#pragma unroll
        for (int off = 16; off; off >>= 1)
            mi = max(mi, __shfl_xor_sync(0xFFFFFFFFu, mi, off));
        if (mi >= 0) { obj = mi; iou = 1.0f; }

        int lab = slab[obj];
        if (iou < 0.5f)         lab = -1;
        if (iou < 0.5f - 0.1f)  lab = 0;
        const bool inc = (lab >= 0);
        const int tcls = (lab < 0) ? 0 : lab;

        // warp log-sum-exp over the 81 scores
        float m = fmaxf(fmaxf(v0, v1), v2);
#pragma unroll
        for (int off = 16; off; off >>= 1)
            m = fmaxf(m, __shfl_xor_sync(0xFFFFFFFFu, m, off));
        float s = expf(v0 - m) + expf(v1 - m) +
                  ((lane < NC - 64) ? expf(v2 - m) : 0.0f);
#pragma unroll
        for (int off = 16; off; off >>= 1)
            s += __shfl_xor_sync(0xFFFFFFFFu, s, off);

        // fetch the target-class score to lane 0 via shuffle
        float vt = (tcls < 32) ? v0 : (tcls < 64 ? v1 : v2);
        float sc_t = __shfl_sync(0xFFFFFFFFu, vt, tcls & 31);

        if (lane == 0) {
            if (inc) {
                float logpt = sc_t - m - logf(s);
                float pt = expf(logpt);
                float om = 1.0f - pt;
                acc_foc += -om * om * logpt;
                cnt_inc++;
            }
            if (lab > 0) {
                float4 g = __ldg(lbase + p);
                float cx = g.x * pc.z * 0.1f + pc.x;
                float cy = g.y * pc.w * 0.1f + pc.y;
                float wd = expf(g.z * 0.2f) * pc.z;
                float ht = expf(g.w * 0.2f) * pc.w;
                float dx1 = cx - wd * 0.5f, dy1 = cy - ht * 0.5f;
                float dx2 = cx + wd * 0.5f, dy2 = cy + ht * 0.5f;
                float4 tb = sbx[obj];
                float lx = fmaxf(dx1, tb.x), ly = fmaxf(dy1, tb.y);
                float hx = fminf(dx2, tb.z), hy = fminf(dy2, tb.w);
                float inter = fmaxf(hx - lx, 0.0f) * fmaxf(hy - ly, 0.0f);
                float ap = (dx2 - dx1) * (dy2 - dy1);
                float at = (tb.z - tb.x) * (tb.w - tb.y);
                float iou2 = inter / (ap + at - inter);
                float pcx = (dx1 + dx2) * 0.5f, pcy = (dy1 + dy2) * 0.5f;
                float tcx = (tb.x + tb.z) * 0.5f, tcy = (tb.y + tb.w) * 0.5f;
                float ddx = pcx - tcx, ddy = pcy - tcy;
                float idiag = ddx * ddx + ddy * ddy;
                float ox = fmaxf(fmaxf(dx2, tb.z) - fminf(dx1, tb.x), 0.0f);
                float oy = fmaxf(fmaxf(dy2, tb.w) - fminf(dy1, tb.y), 0.0f);
                float odiag = ox * ox + oy * oy;
                float d = iou2 - idiag / odiag;
                d = fminf(fmaxf(d, -1.0f), 1.0f);
                acc_loc += 1.0f - d;
                cnt_pos++;
            }
        }
    }

    if (lane == 0) {
        red_loc[w] = acc_loc;
        red_foc[w] = acc_foc;
        red_pos[w] = cnt_pos;
        red_inc[w] = cnt_inc;
    }
    __syncthreads();
    if (t == 0) {
        float sl = 0.0f, sf = 0.0f;
        int sp = 0, si = 0;
#pragma unroll
        for (int i = 0; i < 8; i++) {
            sl += red_loc[i]; sf += red_foc[i];
            sp += red_pos[i]; si += red_inc[i];
        }
        atomicAdd(&g_sum_loc, (double)sl);
        atomicAdd(&g_sum_focal, (double)sf);
        atomicAdd(&g_n_pos, (unsigned)sp);
        atomicAdd(&g_n_inc, (unsigned)si);
    }
}

// ---------------------------------------------------------------------------
// Kernel 3: finalize scalar loss
// ---------------------------------------------------------------------------
__global__ void k_final(float* out) {
    double np = (double)g_n_pos;
    double conf = (g_sum_focal / (double)g_n_inc) / np;
    double loc = g_sum_loc / np;
    out[0] = (float)(conf + 25.0 * loc);
}

// ---------------------------------------------------------------------------
extern "C" void kernel_launch(void* const* d_in, const int* in_sizes, int n_in,
                              void* d_out, int out_size) {
    const float4* locs   = (const float4*)d_in[0];
    const float*  scores = (const float*)d_in[1];
    const float4* boxes  = (const float4*)d_in[2];
    const int*    labels = (const int*)d_in[3];
    const float4* priors = (const float4*)d_in[4];

    k_init<<<1, 512>>>();
    k_match<<<dim3(B, 8), 256>>>(boxes, priors);
    k_main<<<dim3(NBLKX, B), 256>>>(locs, scores, boxes, labels, priors);
    k_final<<<1, 1>>>((float*)d_out);
}